// round 1
// baseline (speedup 1.0000x reference)
#include <cuda_runtime.h>
#include <cuda_bf16.h>
#include <math_constants.h>

// ---------------------------------------------------------------------------
// RPE_Attention: x[64,197,768] -> qkv -> per-head attention (+rel pos bias on
// patch block) -> proj.  All fp32 baseline.
// Inputs (metadata order): x, w_qkv[2304,768], w_proj[768,768], b_proj[768],
//                          rpb_table[729,12], rel_idx[196*196] (int32)
// Output: [64,197,768] float32
// ---------------------------------------------------------------------------

#define BATCH 64
#define NQ    197
#define CDIM  768
#define NH    12
#define HD    64
#define NP    196

// scratch (no cudaMalloc allowed)
__device__ float g_qkv[(size_t)BATCH * NQ * 3 * CDIM];   // [B,N,2304]
__device__ float g_attn[(size_t)BATCH * NQ * CDIM];      // [B,N,768]

// ---------------------------------------------------------------------------
// SGEMM (NT): C[m][n] = sum_k A[m*K+k] * B[n*K+k] (+ bias[n])
// BM=BN=128, BK=8, 256 threads, 8x8 microtile, register prefetch.
// ---------------------------------------------------------------------------
#define BM 128
#define BN 128
#define BK 8

__global__ __launch_bounds__(256) void sgemm_nt(
    const float* __restrict__ A, const float* __restrict__ B,
    const float* __restrict__ bias, float* __restrict__ C,
    int M, int N, int K)
{
    __shared__ float As[BK][BM];
    __shared__ float Bs[BK][BN];

    const int tid = threadIdx.x;
    const int bm = blockIdx.y * BM;
    const int bn = blockIdx.x * BN;

    const int lr = tid >> 1;          // 0..127 row within tile
    const int lc = (tid & 1) * 4;     // 0 or 4 within k-slab

    const bool arow_ok = (bm + lr) < M;
    const bool brow_ok = (bn + lr) < N;

    const float* Aptr = A + (size_t)(bm + lr) * K + lc;
    const float* Bptr = B + (size_t)(bn + lr) * K + lc;

    const int tx = tid & 15;          // n
    const int ty = tid >> 4;          // m

    float acc[8][8];
#pragma unroll
    for (int i = 0; i < 8; i++)
#pragma unroll
        for (int j = 0; j < 8; j++) acc[i][j] = 0.f;

    float4 av = arow_ok ? *(const float4*)Aptr : make_float4(0.f, 0.f, 0.f, 0.f);
    float4 bv = brow_ok ? *(const float4*)Bptr : make_float4(0.f, 0.f, 0.f, 0.f);

    for (int k0 = 0; k0 < K; k0 += BK) {
        As[lc + 0][lr] = av.x;
        As[lc + 1][lr] = av.y;
        As[lc + 2][lr] = av.z;
        As[lc + 3][lr] = av.w;
        Bs[lc + 0][lr] = bv.x;
        Bs[lc + 1][lr] = bv.y;
        Bs[lc + 2][lr] = bv.z;
        Bs[lc + 3][lr] = bv.w;
        __syncthreads();

        if (k0 + BK < K) {
            av = arow_ok ? *(const float4*)(Aptr + k0 + BK) : make_float4(0.f,0.f,0.f,0.f);
            bv = brow_ok ? *(const float4*)(Bptr + k0 + BK) : make_float4(0.f,0.f,0.f,0.f);
        }

#pragma unroll
        for (int kk = 0; kk < BK; kk++) {
            float4 a0 = *(const float4*)&As[kk][ty * 8];
            float4 a1 = *(const float4*)&As[kk][ty * 8 + 4];
            float4 b0 = *(const float4*)&Bs[kk][tx * 8];
            float4 b1 = *(const float4*)&Bs[kk][tx * 8 + 4];
            float a[8] = {a0.x, a0.y, a0.z, a0.w, a1.x, a1.y, a1.z, a1.w};
            float b[8] = {b0.x, b0.y, b0.z, b0.w, b1.x, b1.y, b1.z, b1.w};
#pragma unroll
            for (int i = 0; i < 8; i++)
#pragma unroll
                for (int j = 0; j < 8; j++) acc[i][j] += a[i] * b[j];
        }
        __syncthreads();
    }

#pragma unroll
    for (int i = 0; i < 8; i++) {
        int row = bm + ty * 8 + i;
        if (row >= M) continue;
#pragma unroll
        for (int j = 0; j < 8; j++) {
            int col = bn + tx * 8 + j;
            if (col < N) {
                float v = acc[i][j];
                if (bias) v += bias[col];
                C[(size_t)row * N + col] = v;
            }
        }
    }
}

// ---------------------------------------------------------------------------
// Attention: one block per (b,h).  K,V resident in smem (padded rows),
// loop over q rows: scores + bias -> block softmax -> PV.
// ---------------------------------------------------------------------------
#define KPAD 65
#define ATTN_SMEM_FLOATS (NQ * KPAD * 2 + 729 + 64 + 256 + 256 + 16)

__global__ __launch_bounds__(256) void attn_kernel(
    const float* __restrict__ qkv, const float* __restrict__ rpb_table,
    const int* __restrict__ rel_idx, float* __restrict__ out)
{
    extern __shared__ float sm[];
    float* Ks     = sm;                    // [197][65]
    float* Vs     = Ks + NQ * KPAD;        // [197][65]
    float* bias_s = Vs + NQ * KPAD;        // [729]
    float* qs     = bias_s + 729;          // [64]
    float* p_s    = qs + 64;               // [256]
    float* acc_s  = p_s + 256;             // [4][64]
    float* red_s  = acc_s + 256;           // [16]

    const int tid = threadIdx.x;
    const int b = blockIdx.x / NH;
    const int h = blockIdx.x % NH;
    const float scale = 0.125f;            // 64^-0.5

    const float* kbase = qkv + (size_t)b * NQ * (3 * CDIM) + CDIM + h * HD;
    const float* vbase = kbase + CDIM;
    const float* qbase = qkv + (size_t)b * NQ * (3 * CDIM) + h * HD;
    float* obase = out + (size_t)b * NQ * CDIM + h * HD;

    for (int i = tid; i < NQ * HD; i += 256) {
        int n = i >> 6, d = i & 63;
        Ks[n * KPAD + d] = kbase[(size_t)n * (3 * CDIM) + d];
        Vs[n * KPAD + d] = vbase[(size_t)n * (3 * CDIM) + d];
    }
    for (int i = tid; i < 729; i += 256) bias_s[i] = rpb_table[i * NH + h];
    __syncthreads();

    const int lane = tid & 31;
    const int wid = tid >> 5;

    for (int q = 0; q < NQ; q++) {
        if (tid < HD) qs[tid] = qbase[(size_t)q * (3 * CDIM) + tid] * scale;
        __syncthreads();

        float s = -CUDART_INF_F;
        if (tid < NQ) {
            float acc = 0.f;
            const float* krow = Ks + tid * KPAD;
#pragma unroll 16
            for (int d = 0; d < HD; d++) acc += qs[d] * krow[d];
            if (q > 0 && tid > 0)
                acc += bias_s[rel_idx[(q - 1) * NP + (tid - 1)]];
            s = acc;
        }

        // block max
        float m = s;
#pragma unroll
        for (int o = 16; o > 0; o >>= 1) m = fmaxf(m, __shfl_xor_sync(0xffffffffu, m, o));
        if (lane == 0) red_s[wid] = m;
        __syncthreads();
        float bmax = red_s[0];
#pragma unroll
        for (int w = 1; w < 8; w++) bmax = fmaxf(bmax, red_s[w]);

        float e = (tid < NQ) ? __expf(s - bmax) : 0.f;
        float wsum = e;
#pragma unroll
        for (int o = 16; o > 0; o >>= 1) wsum += __shfl_xor_sync(0xffffffffu, wsum, o);
        __syncthreads();                     // all done reading red_s (max)
        if (lane == 0) red_s[wid] = wsum;
        __syncthreads();
        float tot = 0.f;
#pragma unroll
        for (int w = 0; w < 8; w++) tot += red_s[w];
        p_s[tid] = e / tot;
        __syncthreads();

        // PV: thread -> (d = tid&63, k-strip = tid>>6)
        {
            int d = tid & 63, part = tid >> 6;
            float acc = 0.f;
            for (int k = part; k < NQ; k += 4) acc += p_s[k] * Vs[k * KPAD + d];
            acc_s[part * 64 + d] = acc;
        }
        __syncthreads();
        if (tid < HD) {
            float o = acc_s[tid] + acc_s[64 + tid] + acc_s[128 + tid] + acc_s[192 + tid];
            obase[(size_t)q * CDIM + tid] = o;
        }
        __syncthreads();
    }
}

// ---------------------------------------------------------------------------
extern "C" void kernel_launch(void* const* d_in, const int* in_sizes, int n_in,
                              void* d_out, int out_size)
{
    const float* x      = (const float*)d_in[0];
    const float* w_qkv  = (const float*)d_in[1];
    const float* w_proj = (const float*)d_in[2];
    const float* b_proj = (const float*)d_in[3];
    const float* rpb    = (const float*)d_in[4];
    const int*   relidx = (const int*)d_in[5];
    float* out = (float*)d_out;

    float* qkv_s;
    float* attn_s;
    cudaGetSymbolAddress((void**)&qkv_s, g_qkv);
    cudaGetSymbolAddress((void**)&attn_s, g_attn);

    const int M = BATCH * NQ;   // 12608

    // 1) QKV GEMM: [M,768] x [2304,768]^T -> [M,2304]
    {
        dim3 grid((3 * CDIM + BN - 1) / BN, (M + BM - 1) / BM);
        sgemm_nt<<<grid, 256>>>(x, w_qkv, nullptr, qkv_s, M, 3 * CDIM, CDIM);
    }

    // 2) attention
    {
        size_t smem = (size_t)ATTN_SMEM_FLOATS * sizeof(float);
        cudaFuncSetAttribute(attn_kernel, cudaFuncAttributeMaxDynamicSharedMemorySize,
                             (int)smem);
        attn_kernel<<<BATCH * NH, 256, smem>>>(qkv_s, rpb, relidx, attn_s);
    }

    // 3) proj GEMM: [M,768] x [768,768]^T + bias -> out
    {
        dim3 grid((CDIM + BN - 1) / BN, (M + BM - 1) / BM);
        sgemm_nt<<<grid, 256>>>(attn_s, w_proj, b_proj, out, M, CDIM, CDIM);
    }
}

// round 4
// speedup vs baseline: 2.0371x; 2.0371x over previous
#include <cuda_runtime.h>
#include <cuda_bf16.h>
#include <math_constants.h>
#include <cstdint>

// ---------------------------------------------------------------------------
// RPE_Attention: x[64,197,768] -> qkv -> per-head attention (+rel pos bias on
// patch block) -> proj.
// GEMMs: tf32 tensor-core (3-term split => fp32-class accuracy).
// Attention: warp-per-(q-row-pair), no block barriers in main loop.
// ---------------------------------------------------------------------------

#define BATCH 64
#define NQ    197
#define CDIM  768
#define NH    12
#define HD    64
#define NP    196

__device__ float g_qkv[(size_t)BATCH * NQ * 3 * CDIM];   // [B,N,2304]
__device__ float g_attn[(size_t)BATCH * NQ * CDIM];      // [B,N,768]

// ===========================================================================
// tf32 tensor-core GEMM (NT): C[m][n] = sum_k A[m*K+k] * B[n*K+k] (+bias[n])
// BM=BN=128, BK=16, 256 threads, 8 warps as 2(m) x 4(n), warp tile 64x32.
// ===========================================================================

__device__ __forceinline__ unsigned smem_u32(const void* p) {
    return (unsigned)__cvta_generic_to_shared(p);
}

__device__ __forceinline__ void cp_async16(unsigned dst, const void* src, bool pred) {
    int sz = pred ? 16 : 0;
    asm volatile("cp.async.cg.shared.global [%0], [%1], 16, %2;\n"
                 :: "r"(dst), "l"(src), "r"(sz));
}
__device__ __forceinline__ void cp_commit() { asm volatile("cp.async.commit_group;\n"); }
__device__ __forceinline__ void cp_wait0()  { asm volatile("cp.async.wait_group 0;\n"); }

__device__ __forceinline__ void split_tf32(float x, uint32_t& hi, uint32_t& lo) {
    uint32_t h;
    asm("cvt.rna.tf32.f32 %0, %1;" : "=r"(h) : "f"(x));
    float rem = x - __uint_as_float(h);
    uint32_t l;
    asm("cvt.rna.tf32.f32 %0, %1;" : "=r"(l) : "f"(rem));
    hi = h; lo = l;
}

__device__ __forceinline__ void mma_tf32(float* d, const uint32_t* a, const uint32_t* b) {
    asm volatile(
        "mma.sync.aligned.m16n8k8.row.col.f32.tf32.tf32.f32 "
        "{%0,%1,%2,%3}, {%4,%5,%6,%7}, {%8,%9}, {%0,%1,%2,%3};"
        : "+f"(d[0]), "+f"(d[1]), "+f"(d[2]), "+f"(d[3])
        : "r"(a[0]), "r"(a[1]), "r"(a[2]), "r"(a[3]), "r"(b[0]), "r"(b[1]));
}

#define GLD 20            // smem row stride in floats (16 + 4 pad)
#define GBUF (128 * GLD)  // floats per buffer

__global__ __launch_bounds__(256) void gemm_tf32(
    const float* __restrict__ A, const float* __restrict__ B,
    const float* __restrict__ bias, float* __restrict__ C,
    int M, int N, int K)
{
    __shared__ float As[2][GBUF];
    __shared__ float Bs[2][GBUF];

    const int tid  = threadIdx.x;
    const int lane = tid & 31;
    const int wid  = tid >> 5;
    const int wm   = wid & 1;        // 0..1  (64-row band)
    const int wn   = wid >> 1;       // 0..3  (32-col band)
    const int bm   = blockIdx.y * 128;
    const int bn   = blockIdx.x * 128;

    // loader: each thread copies 2 consecutive float4 (one half row of 8 floats)
    const int lrow = tid >> 1;              // 0..127
    const int lcf  = (tid & 1) * 8;         // float offset 0 or 8
    const bool aok = (bm + lrow) < M;
    const bool bok = (bn + lrow) < N;
    const float* Ag = A + (size_t)(aok ? bm + lrow : 0) * K + lcf;
    const float* Bg = B + (size_t)(bok ? bn + lrow : 0) * K + lcf;
    const unsigned AsAddr = smem_u32(&As[0][0]) + (unsigned)(lrow * GLD + lcf) * 4u;
    const unsigned BsAddr = smem_u32(&Bs[0][0]) + (unsigned)(lrow * GLD + lcf) * 4u;
    const unsigned BUFB   = GBUF * 4u;

    const int nIter = K / 16;

    // prologue: tile 0
    cp_async16(AsAddr,      Ag,     aok);
    cp_async16(AsAddr + 16, Ag + 4, aok);
    cp_async16(BsAddr,      Bg,     bok);
    cp_async16(BsAddr + 16, Bg + 4, bok);
    cp_commit();

    float acc[4][4][4];
#pragma unroll
    for (int i = 0; i < 4; i++)
#pragma unroll
        for (int j = 0; j < 4; j++)
#pragma unroll
            for (int r = 0; r < 4; r++) acc[i][j][r] = 0.f;

    const int g = lane >> 2;
    const int t = lane & 3;

    for (int it = 0; it < nIter; it++) {
        cp_wait0();
        __syncthreads();

        if (it + 1 < nIter) {
            const int ko = (it + 1) * 16;
            const unsigned off = (unsigned)((it + 1) & 1) * BUFB;
            cp_async16(AsAddr + off,      Ag + ko,     aok);
            cp_async16(AsAddr + off + 16, Ag + ko + 4, aok);
            cp_async16(BsAddr + off,      Bg + ko,     bok);
            cp_async16(BsAddr + off + 16, Bg + ko + 4, bok);
            cp_commit();
        }

        const float* as = As[it & 1];
        const float* bs = Bs[it & 1];

#pragma unroll
        for (int ks = 0; ks < 16; ks += 8) {
            uint32_t ahi[4][4], alo[4][4], bhi[4][2], blo[4][2];
#pragma unroll
            for (int mt = 0; mt < 4; mt++) {
                const float* base = as + (wm * 64 + mt * 16 + g) * GLD + ks + t;
                split_tf32(base[0],           ahi[mt][0], alo[mt][0]);
                split_tf32(base[8 * GLD],     ahi[mt][1], alo[mt][1]);
                split_tf32(base[4],           ahi[mt][2], alo[mt][2]);
                split_tf32(base[8 * GLD + 4], ahi[mt][3], alo[mt][3]);
            }
#pragma unroll
            for (int nt = 0; nt < 4; nt++) {
                const float* base = bs + (wn * 32 + nt * 8 + g) * GLD + ks + t;
                split_tf32(base[0], bhi[nt][0], blo[nt][0]);
                split_tf32(base[4], bhi[nt][1], blo[nt][1]);
            }
#pragma unroll
            for (int mt = 0; mt < 4; mt++)
#pragma unroll
                for (int nt = 0; nt < 4; nt++) {
                    mma_tf32(acc[mt][nt], ahi[mt], bhi[nt]);
                    mma_tf32(acc[mt][nt], alo[mt], bhi[nt]);
                    mma_tf32(acc[mt][nt], ahi[mt], blo[nt]);
                }
        }
        __syncthreads();
    }

    // epilogue
#pragma unroll
    for (int mt = 0; mt < 4; mt++) {
        const int row0 = bm + wm * 64 + mt * 16 + g;
#pragma unroll
        for (int nt = 0; nt < 4; nt++) {
            const int col = bn + wn * 32 + nt * 8 + t * 2;
            float bv0 = bias ? bias[col]     : 0.f;
            float bv1 = bias ? bias[col + 1] : 0.f;
            if (row0 < M) {
                float2 v = make_float2(acc[mt][nt][0] + bv0, acc[mt][nt][1] + bv1);
                *(float2*)&C[(size_t)row0 * N + col] = v;
            }
            if (row0 + 8 < M) {
                float2 v = make_float2(acc[mt][nt][2] + bv0, acc[mt][nt][3] + bv1);
                *(float2*)&C[(size_t)(row0 + 8) * N + col] = v;
            }
        }
    }
}

// ===========================================================================
// Attention: block per (b,h), 512 threads = 16 warps.
// Each warp processes a PAIR of q rows (amortizes K reads).
// No block-wide barriers in the main loop.
// ===========================================================================
#define AT_THREADS 512
#define AT_WARPS   16
#define KROWS      224      // padded row count (>= 7*32)
#define RS         17       // float4 per K/V row (16 + 1 pad)
#define PBS        224      // pbuf stride

__global__ __launch_bounds__(AT_THREADS) void attn_warp(
    const float* __restrict__ qkv, const float* __restrict__ rpb_table,
    const int* __restrict__ rel_idx, float* __restrict__ out)
{
    extern __shared__ float4 sm4[];
    float4* K4     = sm4;                          // [KROWS][RS]
    float4* V4     = K4 + KROWS * RS;              // [KROWS][RS]
    float4* QB     = V4 + KROWS * RS;              // [AT_WARPS][2][RS]
    float*  bias_s = (float*)(QB + AT_WARPS * 2 * RS);   // 736
    float*  pbuf   = bias_s + 736;                 // [AT_WARPS][2][PBS]

    const int tid  = threadIdx.x;
    const int lane = tid & 31;
    const int wid  = tid >> 5;
    const int b = blockIdx.x / NH;
    const int h = blockIdx.x % NH;

    const float* kbase = qkv + (size_t)b * NQ * (3 * CDIM) + CDIM + h * HD;
    const float* vbase = kbase + CDIM;
    const float* qbase = qkv + (size_t)b * NQ * (3 * CDIM) + h * HD;
    float* obase = out + (size_t)b * NQ * CDIM + h * HD;

    for (int i = tid; i < NQ * 16; i += AT_THREADS) {
        int n = i >> 4, d4 = i & 15;
        K4[n * RS + d4] = ((const float4*)(kbase + (size_t)n * (3 * CDIM)))[d4];
        V4[n * RS + d4] = ((const float4*)(vbase + (size_t)n * (3 * CDIM)))[d4];
    }
    for (int i = tid; i < 729; i += AT_THREADS) bias_s[i] = rpb_table[i * NH + h];
    __syncthreads();

    for (int p = wid; p < 99; p += AT_WARPS) {
        const int q0 = 2 * p;
        const int q1 = 2 * p + 1;
        const bool q1ok = (q1 < NQ);

        // load scaled q rows into per-warp smem
        {
            int r  = lane >> 4;                 // 0 -> q0, 1 -> q1
            int d4 = lane & 15;
            int qq = (r == 0) ? q0 : (q1ok ? q1 : q0);
            float4 v = ((const float4*)(qbase + (size_t)qq * (3 * CDIM)))[d4];
            v.x *= 0.125f; v.y *= 0.125f; v.z *= 0.125f; v.w *= 0.125f;
            QB[(wid * 2 + r) * RS + d4] = v;
        }
        __syncwarp();

        float s0[7], s1[7];
#pragma unroll
        for (int c = 0; c < 7; c++) { s0[c] = 0.f; s1[c] = 0.f; }

#pragma unroll
        for (int d4 = 0; d4 < 16; d4++) {
            const float4 qa = QB[(wid * 2 + 0) * RS + d4];
            const float4 qc = QB[(wid * 2 + 1) * RS + d4];
#pragma unroll
            for (int c = 0; c < 7; c++) {
                const int j = lane + 32 * c;          // < 224, in-bounds of K4
                const float4 kv = K4[j * RS + d4];
                s0[c] += qa.x * kv.x + qa.y * kv.y + qa.z * kv.z + qa.w * kv.w;
                s1[c] += qc.x * kv.x + qc.y * kv.y + qc.z * kv.z + qc.w * kv.w;
            }
        }

        // bias + mask
#pragma unroll
        for (int c = 0; c < 7; c++) {
            const int j = lane + 32 * c;
            if (j < NQ) {
                if (j > 0) {
                    if (q0 > 0)
                        s0[c] += bias_s[rel_idx[(q0 - 1) * NP + (j - 1)]];
                    int q1r = q1ok ? (q1 - 1) : 0;
                    s1[c] += bias_s[rel_idx[q1r * NP + (j - 1)]];
                }
            } else {
                s0[c] = -CUDART_INF_F;
                s1[c] = -CUDART_INF_F;
            }
        }

        // softmax (warp-level)
        float m0 = s0[0], m1 = s1[0];
#pragma unroll
        for (int c = 1; c < 7; c++) { m0 = fmaxf(m0, s0[c]); m1 = fmaxf(m1, s1[c]); }
#pragma unroll
        for (int o = 16; o > 0; o >>= 1) {
            m0 = fmaxf(m0, __shfl_xor_sync(0xffffffffu, m0, o));
            m1 = fmaxf(m1, __shfl_xor_sync(0xffffffffu, m1, o));
        }
        float t0 = 0.f, t1 = 0.f;
#pragma unroll
        for (int c = 0; c < 7; c++) {
            s0[c] = __expf(s0[c] - m0);
            s1[c] = __expf(s1[c] - m1);
            t0 += s0[c]; t1 += s1[c];
        }
#pragma unroll
        for (int o = 16; o > 0; o >>= 1) {
            t0 += __shfl_xor_sync(0xffffffffu, t0, o);
            t1 += __shfl_xor_sync(0xffffffffu, t1, o);
        }
        const float inv0 = 1.f / t0;
        const float inv1 = 1.f / t1;
#pragma unroll
        for (int c = 0; c < 7; c++) {
            const int j = lane + 32 * c;
            if (j < NQ) {
                pbuf[(wid * 2 + 0) * PBS + j] = s0[c] * inv0;
                pbuf[(wid * 2 + 1) * PBS + j] = s1[c] * inv1;
            }
        }
        __syncwarp();

        // PV: lane -> d4 = lane&15, key parity = lane>>4
        {
            const int d4 = lane & 15;
            const int cc = lane >> 4;
            float4 a0 = make_float4(0.f, 0.f, 0.f, 0.f);
            float4 a1 = make_float4(0.f, 0.f, 0.f, 0.f);
            for (int j = cc; j < NQ; j += 2) {
                const float p0 = pbuf[(wid * 2 + 0) * PBS + j];
                const float p1 = pbuf[(wid * 2 + 1) * PBS + j];
                const float4 v = V4[j * RS + d4];
                a0.x += p0 * v.x; a0.y += p0 * v.y; a0.z += p0 * v.z; a0.w += p0 * v.w;
                a1.x += p1 * v.x; a1.y += p1 * v.y; a1.z += p1 * v.z; a1.w += p1 * v.w;
            }
            a0.x += __shfl_xor_sync(0xffffffffu, a0.x, 16);
            a0.y += __shfl_xor_sync(0xffffffffu, a0.y, 16);
            a0.z += __shfl_xor_sync(0xffffffffu, a0.z, 16);
            a0.w += __shfl_xor_sync(0xffffffffu, a0.w, 16);
            a1.x += __shfl_xor_sync(0xffffffffu, a1.x, 16);
            a1.y += __shfl_xor_sync(0xffffffffu, a1.y, 16);
            a1.z += __shfl_xor_sync(0xffffffffu, a1.z, 16);
            a1.w += __shfl_xor_sync(0xffffffffu, a1.w, 16);

            if (lane < 16) {
                ((float4*)(obase + (size_t)q0 * CDIM))[d4] = a0;
            } else if (q1ok) {
                ((float4*)(obase + (size_t)q1 * CDIM))[d4] = a1;
            }
        }
        __syncwarp();
    }
}

// ===========================================================================
extern "C" void kernel_launch(void* const* d_in, const int* in_sizes, int n_in,
                              void* d_out, int out_size)
{
    const float* x      = (const float*)d_in[0];
    const float* w_qkv  = (const float*)d_in[1];
    const float* w_proj = (const float*)d_in[2];
    const float* b_proj = (const float*)d_in[3];
    const float* rpb    = (const float*)d_in[4];
    const int*   relidx = (const int*)d_in[5];
    float* out = (float*)d_out;

    float* qkv_s;
    float* attn_s;
    cudaGetSymbolAddress((void**)&qkv_s, g_qkv);
    cudaGetSymbolAddress((void**)&attn_s, g_attn);

    const int M = BATCH * NQ;   // 12608

    // 1) QKV GEMM: [M,768] x [2304,768]^T -> [M,2304]
    {
        dim3 grid((3 * CDIM) / 128, (M + 127) / 128);
        gemm_tf32<<<grid, 256>>>(x, w_qkv, nullptr, qkv_s, M, 3 * CDIM, CDIM);
    }

    // 2) attention
    {
        size_t smem = (size_t)(KROWS * RS * 2 + AT_WARPS * 2 * RS) * sizeof(float4)
                    + (size_t)(736 + AT_WARPS * 2 * PBS) * sizeof(float);
        cudaFuncSetAttribute(attn_warp, cudaFuncAttributeMaxDynamicSharedMemorySize,
                             (int)smem);
        attn_warp<<<BATCH * NH, AT_THREADS, smem>>>(qkv_s, rpb, relidx, attn_s);
    }

    // 3) proj GEMM: [M,768] x [768,768]^T + bias -> out
    {
        dim3 grid(CDIM / 128, (M + 127) / 128);
        gemm_tf32<<<grid, 256>>>(attn_s, w_proj, b_proj, out, M, CDIM, CDIM);
    }
}

// round 5
// speedup vs baseline: 2.6037x; 1.2781x over previous
#include <cuda_runtime.h>
#include <cuda_fp16.h>
#include <math_constants.h>
#include <cstdint>

// ---------------------------------------------------------------------------
// RPE_Attention: x[64,197,768] -> qkv -> per-head attention (+rel pos bias) ->
// proj.
// GEMMs: fp16 tensor-core, 3-term Markidis split (AhiBhi+AloBhi+AhiBlo) with
// operands PRE-SPLIT in HBM (no CVT work in the GEMM inner loop).
// Attention: warp-per-(q-row-pair), fp32, smem-resident K/V.
// ---------------------------------------------------------------------------

#define BATCH 64
#define NQ    197
#define CDIM  768
#define NH    12
#define HD    64
#define NP    196
#define MTOT  (BATCH * NQ)          // 12608

// fp32 scratch
__device__ float g_qkv[(size_t)MTOT * 3 * CDIM];
__device__ float g_attn[(size_t)MTOT * CDIM];

// pre-split fp16 planes
__device__ __half2 g_xhi[(size_t)MTOT * CDIM / 2];
__device__ __half2 g_xlo[(size_t)MTOT * CDIM / 2];
__device__ __half2 g_whi[(size_t)3 * CDIM * CDIM / 2];
__device__ __half2 g_wlo[(size_t)3 * CDIM * CDIM / 2];
__device__ __half2 g_phi[(size_t)CDIM * CDIM / 2];
__device__ __half2 g_plo[(size_t)CDIM * CDIM / 2];
__device__ __half2 g_ahi[(size_t)MTOT * CDIM / 2];
__device__ __half2 g_alo[(size_t)MTOT * CDIM / 2];

// ===========================================================================
// split: fp32 -> (hi, lo) fp16 planes.  hi = h(x), lo = h(x - f(hi)).
// ===========================================================================
__global__ void split_h(const float4* __restrict__ src, __half2* __restrict__ hi,
                        __half2* __restrict__ lo, int n4)
{
    int i = blockIdx.x * blockDim.x + threadIdx.x;
    if (i >= n4) return;
    float4 v = src[i];
    __half2 h0 = __floats2half2_rn(v.x, v.y);
    __half2 h1 = __floats2half2_rn(v.z, v.w);
    float2 f0 = __half22float2(h0);
    float2 f1 = __half22float2(h1);
    __half2 l0 = __floats2half2_rn(v.x - f0.x, v.y - f0.y);
    __half2 l1 = __floats2half2_rn(v.z - f1.x, v.w - f1.y);
    hi[2 * i]     = h0;
    hi[2 * i + 1] = h1;
    lo[2 * i]     = l0;
    lo[2 * i + 1] = l1;
}

// ===========================================================================
// fp16-split GEMM (NT): C[m][n] = sum_k A[m][k]*B[n][k] (+bias[n])
// BM=BN=128, BK=32, 128 threads = 4 warps (2x2), warp tile 64x64.
// ldmatrix fragment loads, cp.async double buffer.
// ===========================================================================

__device__ __forceinline__ unsigned smem_u32(const void* p) {
    return (unsigned)__cvta_generic_to_shared(p);
}
__device__ __forceinline__ void cp_async16(unsigned dst, const void* src, bool pred) {
    int sz = pred ? 16 : 0;
    asm volatile("cp.async.cg.shared.global [%0], [%1], 16, %2;\n"
                 :: "r"(dst), "l"(src), "r"(sz));
}
__device__ __forceinline__ void cp_commit() { asm volatile("cp.async.commit_group;\n"); }
__device__ __forceinline__ void cp_wait0()  { asm volatile("cp.async.wait_group 0;\n"); }

__device__ __forceinline__ void ldsm_x4(uint32_t* r, unsigned a) {
    asm volatile("ldmatrix.sync.aligned.m8n8.x4.shared.b16 {%0,%1,%2,%3}, [%4];"
                 : "=r"(r[0]), "=r"(r[1]), "=r"(r[2]), "=r"(r[3]) : "r"(a));
}
__device__ __forceinline__ void ldsm_x2(uint32_t& r0, uint32_t& r1, unsigned a) {
    asm volatile("ldmatrix.sync.aligned.m8n8.x2.shared.b16 {%0,%1}, [%2];"
                 : "=r"(r0), "=r"(r1) : "r"(a));
}
__device__ __forceinline__ void mma_f16(float* d, const uint32_t* a, const uint32_t* b) {
    asm volatile(
        "mma.sync.aligned.m16n8k16.row.col.f32.f16.f16.f32 "
        "{%0,%1,%2,%3}, {%4,%5,%6,%7}, {%8,%9}, {%0,%1,%2,%3};"
        : "+f"(d[0]), "+f"(d[1]), "+f"(d[2]), "+f"(d[3])
        : "r"(a[0]), "r"(a[1]), "r"(a[2]), "r"(a[3]), "r"(b[0]), "r"(b[1]));
}

#define APAD   40                     // smem row stride (halfs): 32 + 8
#define PLANE  (128 * APAD)           // halfs per plane  (5120)
#define GBUFH  (2 * PLANE)            // halfs per buffer (hi+lo)
#define BBASE  (4 * PLANE)            // B region offset (halfs)
#define GSMEM  (8 * PLANE * 2)        // total bytes: 81920

__global__ __launch_bounds__(128, 2) void gemm_f16s(
    const __half* __restrict__ Ahi, const __half* __restrict__ Alo,
    const __half* __restrict__ Bhi, const __half* __restrict__ Blo,
    const float* __restrict__ bias, float* __restrict__ C,
    int M, int N, int K)
{
    extern __shared__ __half smg[];

    const int tid  = threadIdx.x;
    const int lane = tid & 31;
    const int wid  = tid >> 5;
    const int wm   = wid & 1;          // 64-row band
    const int wn   = wid >> 1;         // 64-col band
    const int bm   = blockIdx.y * 128;
    const int bn   = blockIdx.x * 128;

    // loader: thread -> one row (64B per plane per matrix)
    const bool aok = (bm + tid) < M;
    const __half* gA0 = Ahi + (size_t)(aok ? bm + tid : 0) * K;
    const __half* gA1 = Alo + (size_t)(aok ? bm + tid : 0) * K;
    const __half* gB0 = Bhi + (size_t)(bn + tid) * K;
    const __half* gB1 = Blo + (size_t)(bn + tid) * K;

    const unsigned a0Addr = smem_u32(smg + tid * APAD);
    const unsigned a1Addr = a0Addr + PLANE * 2;
    const unsigned b0Addr = smem_u32(smg + BBASE + tid * APAD);
    const unsigned b1Addr = b0Addr + PLANE * 2;
    const unsigned BUFB   = GBUFH * 2;   // byte stride between buffers

    const int nIter = K / 32;

    float acc[4][8][4];
#pragma unroll
    for (int i = 0; i < 4; i++)
#pragma unroll
        for (int j = 0; j < 8; j++)
#pragma unroll
            for (int r = 0; r < 4; r++) acc[i][j][r] = 0.f;

    // prologue
    {
#pragma unroll
        for (int s = 0; s < 4; s++) {
            cp_async16(a0Addr + s * 16, gA0 + s * 8, aok);
            cp_async16(a1Addr + s * 16, gA1 + s * 8, aok);
            cp_async16(b0Addr + s * 16, gB0 + s * 8, true);
            cp_async16(b1Addr + s * 16, gB1 + s * 8, true);
        }
        cp_commit();
    }

    for (int it = 0; it < nIter; it++) {
        cp_wait0();
        __syncthreads();

        if (it + 1 < nIter) {
            const int k0 = (it + 1) * 32;
            const unsigned off = (unsigned)((it + 1) & 1) * BUFB;
#pragma unroll
            for (int s = 0; s < 4; s++) {
                cp_async16(a0Addr + off + s * 16, gA0 + k0 + s * 8, aok);
                cp_async16(a1Addr + off + s * 16, gA1 + k0 + s * 8, aok);
                cp_async16(b0Addr + off + s * 16, gB0 + k0 + s * 8, true);
                cp_async16(b1Addr + off + s * 16, gB1 + k0 + s * 8, true);
            }
            cp_commit();
        }

        const __half* sa0 = smg + (it & 1) * GBUFH;
        const __half* sa1 = sa0 + PLANE;
        const __half* sb0 = smg + BBASE + (it & 1) * GBUFH;
        const __half* sb1 = sb0 + PLANE;

#pragma unroll
        for (int ks = 0; ks < 2; ks++) {
            uint32_t bh[8][2], bl[8][2];
#pragma unroll
            for (int nt = 0; nt < 8; nt++) {
                const int row = wn * 64 + nt * 8 + (lane & 7);
                const int col = ks * 16 + ((lane >> 3) & 1) * 8;
                ldsm_x2(bh[nt][0], bh[nt][1], smem_u32(sb0 + row * APAD + col));
                ldsm_x2(bl[nt][0], bl[nt][1], smem_u32(sb1 + row * APAD + col));
            }
#pragma unroll
            for (int mt = 0; mt < 4; mt++) {
                const int row = wm * 64 + mt * 16 + (lane & 15);
                const int col = ks * 16 + (lane >> 4) * 8;
                uint32_t ah[4], al[4];
                ldsm_x4(ah, smem_u32(sa0 + row * APAD + col));
                ldsm_x4(al, smem_u32(sa1 + row * APAD + col));
#pragma unroll
                for (int nt = 0; nt < 8; nt++) {
                    mma_f16(acc[mt][nt], ah, bh[nt]);
                    mma_f16(acc[mt][nt], al, bh[nt]);
                    mma_f16(acc[mt][nt], ah, bl[nt]);
                }
            }
        }
    }

    // epilogue
    const int g = lane >> 2;
    const int t = lane & 3;
#pragma unroll
    for (int mt = 0; mt < 4; mt++) {
        const int r0 = bm + wm * 64 + mt * 16 + g;
#pragma unroll
        for (int nt = 0; nt < 8; nt++) {
            const int col = bn + wn * 64 + nt * 8 + 2 * t;
            const float bv0 = bias ? bias[col]     : 0.f;
            const float bv1 = bias ? bias[col + 1] : 0.f;
            if (r0 < M) {
                float2 v = make_float2(acc[mt][nt][0] + bv0, acc[mt][nt][1] + bv1);
                *(float2*)&C[(size_t)r0 * N + col] = v;
            }
            if (r0 + 8 < M) {
                float2 v = make_float2(acc[mt][nt][2] + bv0, acc[mt][nt][3] + bv1);
                *(float2*)&C[(size_t)(r0 + 8) * N + col] = v;
            }
        }
    }
}

// ===========================================================================
// Attention: block per (b,h), 512 threads = 16 warps, warp-per-q-row-pair.
// ===========================================================================
#define AT_THREADS 512
#define AT_WARPS   16
#define KROWS      224
#define RS         17
#define PBS        224

__global__ __launch_bounds__(AT_THREADS) void attn_warp(
    const float* __restrict__ qkv, const float* __restrict__ rpb_table,
    const int* __restrict__ rel_idx, float* __restrict__ out)
{
    extern __shared__ float4 sm4[];
    float4* K4     = sm4;
    float4* V4     = K4 + KROWS * RS;
    float4* QB     = V4 + KROWS * RS;
    float*  bias_s = (float*)(QB + AT_WARPS * 2 * RS);
    float*  pbuf   = bias_s + 736;

    const int tid  = threadIdx.x;
    const int lane = tid & 31;
    const int wid  = tid >> 5;
    const int b = blockIdx.x / NH;
    const int h = blockIdx.x % NH;

    const float* kbase = qkv + (size_t)b * NQ * (3 * CDIM) + CDIM + h * HD;
    const float* vbase = kbase + CDIM;
    const float* qbase = qkv + (size_t)b * NQ * (3 * CDIM) + h * HD;
    float* obase = out + (size_t)b * NQ * CDIM + h * HD;

    for (int i = tid; i < NQ * 16; i += AT_THREADS) {
        int n = i >> 4, d4 = i & 15;
        K4[n * RS + d4] = ((const float4*)(kbase + (size_t)n * (3 * CDIM)))[d4];
        V4[n * RS + d4] = ((const float4*)(vbase + (size_t)n * (3 * CDIM)))[d4];
    }
    for (int i = tid; i < 729; i += AT_THREADS) bias_s[i] = rpb_table[i * NH + h];
    __syncthreads();

    for (int p = wid; p < 99; p += AT_WARPS) {
        const int q0 = 2 * p;
        const int q1 = 2 * p + 1;
        const bool q1ok = (q1 < NQ);

        {
            int r  = lane >> 4;
            int d4 = lane & 15;
            int qq = (r == 0) ? q0 : (q1ok ? q1 : q0);
            float4 v = ((const float4*)(qbase + (size_t)qq * (3 * CDIM)))[d4];
            v.x *= 0.125f; v.y *= 0.125f; v.z *= 0.125f; v.w *= 0.125f;
            QB[(wid * 2 + r) * RS + d4] = v;
        }
        __syncwarp();

        float s0[7], s1[7];
#pragma unroll
        for (int c = 0; c < 7; c++) { s0[c] = 0.f; s1[c] = 0.f; }

#pragma unroll
        for (int d4 = 0; d4 < 16; d4++) {
            const float4 qa = QB[(wid * 2 + 0) * RS + d4];
            const float4 qc = QB[(wid * 2 + 1) * RS + d4];
#pragma unroll
            for (int c = 0; c < 7; c++) {
                const int j = lane + 32 * c;
                const float4 kv = K4[j * RS + d4];
                s0[c] += qa.x * kv.x + qa.y * kv.y + qa.z * kv.z + qa.w * kv.w;
                s1[c] += qc.x * kv.x + qc.y * kv.y + qc.z * kv.z + qc.w * kv.w;
            }
        }

#pragma unroll
        for (int c = 0; c < 7; c++) {
            const int j = lane + 32 * c;
            if (j < NQ) {
                if (j > 0) {
                    if (q0 > 0)
                        s0[c] += bias_s[rel_idx[(q0 - 1) * NP + (j - 1)]];
                    int q1r = q1ok ? (q1 - 1) : 0;
                    s1[c] += bias_s[rel_idx[q1r * NP + (j - 1)]];
                }
            } else {
                s0[c] = -CUDART_INF_F;
                s1[c] = -CUDART_INF_F;
            }
        }

        float m0 = s0[0], m1 = s1[0];
#pragma unroll
        for (int c = 1; c < 7; c++) { m0 = fmaxf(m0, s0[c]); m1 = fmaxf(m1, s1[c]); }
#pragma unroll
        for (int o = 16; o > 0; o >>= 1) {
            m0 = fmaxf(m0, __shfl_xor_sync(0xffffffffu, m0, o));
            m1 = fmaxf(m1, __shfl_xor_sync(0xffffffffu, m1, o));
        }
        float t0 = 0.f, t1 = 0.f;
#pragma unroll
        for (int c = 0; c < 7; c++) {
            s0[c] = __expf(s0[c] - m0);
            s1[c] = __expf(s1[c] - m1);
            t0 += s0[c]; t1 += s1[c];
        }
#pragma unroll
        for (int o = 16; o > 0; o >>= 1) {
            t0 += __shfl_xor_sync(0xffffffffu, t0, o);
            t1 += __shfl_xor_sync(0xffffffffu, t1, o);
        }
        const float inv0 = 1.f / t0;
        const float inv1 = 1.f / t1;
#pragma unroll
        for (int c = 0; c < 7; c++) {
            const int j = lane + 32 * c;
            if (j < NQ) {
                pbuf[(wid * 2 + 0) * PBS + j] = s0[c] * inv0;
                pbuf[(wid * 2 + 1) * PBS + j] = s1[c] * inv1;
            }
        }
        __syncwarp();

        {
            const int d4 = lane & 15;
            const int cc = lane >> 4;
            float4 a0 = make_float4(0.f, 0.f, 0.f, 0.f);
            float4 a1 = make_float4(0.f, 0.f, 0.f, 0.f);
            for (int j = cc; j < NQ; j += 2) {
                const float p0 = pbuf[(wid * 2 + 0) * PBS + j];
                const float p1 = pbuf[(wid * 2 + 1) * PBS + j];
                const float4 v = V4[j * RS + d4];
                a0.x += p0 * v.x; a0.y += p0 * v.y; a0.z += p0 * v.z; a0.w += p0 * v.w;
                a1.x += p1 * v.x; a1.y += p1 * v.y; a1.z += p1 * v.z; a1.w += p1 * v.w;
            }
            a0.x += __shfl_xor_sync(0xffffffffu, a0.x, 16);
            a0.y += __shfl_xor_sync(0xffffffffu, a0.y, 16);
            a0.z += __shfl_xor_sync(0xffffffffu, a0.z, 16);
            a0.w += __shfl_xor_sync(0xffffffffu, a0.w, 16);
            a1.x += __shfl_xor_sync(0xffffffffu, a1.x, 16);
            a1.y += __shfl_xor_sync(0xffffffffu, a1.y, 16);
            a1.z += __shfl_xor_sync(0xffffffffu, a1.z, 16);
            a1.w += __shfl_xor_sync(0xffffffffu, a1.w, 16);

            if (lane < 16) {
                ((float4*)(obase + (size_t)q0 * CDIM))[d4] = a0;
            } else if (q1ok) {
                ((float4*)(obase + (size_t)q1 * CDIM))[d4] = a1;
            }
        }
        __syncwarp();
    }
}

// ===========================================================================
extern "C" void kernel_launch(void* const* d_in, const int* in_sizes, int n_in,
                              void* d_out, int out_size)
{
    const float* x      = (const float*)d_in[0];
    const float* w_qkv  = (const float*)d_in[1];
    const float* w_proj = (const float*)d_in[2];
    const float* b_proj = (const float*)d_in[3];
    const float* rpb    = (const float*)d_in[4];
    const int*   relidx = (const int*)d_in[5];
    float* out = (float*)d_out;

    float *qkv_s, *attn_s;
    __half2 *xhi, *xlo, *whi, *wlo, *phi, *plo, *ahi, *alo;
    cudaGetSymbolAddress((void**)&qkv_s, g_qkv);
    cudaGetSymbolAddress((void**)&attn_s, g_attn);
    cudaGetSymbolAddress((void**)&xhi, g_xhi);
    cudaGetSymbolAddress((void**)&xlo, g_xlo);
    cudaGetSymbolAddress((void**)&whi, g_whi);
    cudaGetSymbolAddress((void**)&wlo, g_wlo);
    cudaGetSymbolAddress((void**)&phi, g_phi);
    cudaGetSymbolAddress((void**)&plo, g_plo);
    cudaGetSymbolAddress((void**)&ahi, g_ahi);
    cudaGetSymbolAddress((void**)&alo, g_alo);

    const int M = MTOT;   // 12608

    // 0) pre-split x, w_qkv, w_proj
    {
        int n4 = M * CDIM / 4;
        split_h<<<(n4 + 255) / 256, 256>>>((const float4*)x, xhi, xlo, n4);
        n4 = 3 * CDIM * CDIM / 4;
        split_h<<<(n4 + 255) / 256, 256>>>((const float4*)w_qkv, whi, wlo, n4);
        n4 = CDIM * CDIM / 4;
        split_h<<<(n4 + 255) / 256, 256>>>((const float4*)w_proj, phi, plo, n4);
    }

    cudaFuncSetAttribute(gemm_f16s, cudaFuncAttributeMaxDynamicSharedMemorySize, GSMEM);

    // 1) QKV GEMM
    {
        dim3 grid((3 * CDIM) / 128, (M + 127) / 128);
        gemm_f16s<<<grid, 128, GSMEM>>>((const __half*)xhi, (const __half*)xlo,
                                        (const __half*)whi, (const __half*)wlo,
                                        nullptr, qkv_s, M, 3 * CDIM, CDIM);
    }

    // 2) attention
    {
        size_t smem = (size_t)(KROWS * RS * 2 + AT_WARPS * 2 * RS) * sizeof(float4)
                    + (size_t)(736 + AT_WARPS * 2 * PBS) * sizeof(float);
        cudaFuncSetAttribute(attn_warp, cudaFuncAttributeMaxDynamicSharedMemorySize,
                             (int)smem);
        attn_warp<<<BATCH * NH, AT_THREADS, smem>>>(qkv_s, rpb, relidx, attn_s);
    }

    // 3) split attention output, then proj GEMM
    {
        int n4 = M * CDIM / 4;
        split_h<<<(n4 + 255) / 256, 256>>>((const float4*)attn_s, ahi, alo, n4);
        dim3 grid(CDIM / 128, (M + 127) / 128);
        gemm_f16s<<<grid, 128, GSMEM>>>((const __half*)ahi, (const __half*)alo,
                                        (const __half*)phi, (const __half*)plo,
                                        b_proj, out, M, CDIM, CDIM);
    }
}

// round 6
// speedup vs baseline: 3.0168x; 1.1587x over previous
#include <cuda_runtime.h>
#include <cuda_fp16.h>
#include <math_constants.h>
#include <cstdint>

// ---------------------------------------------------------------------------
// RPE_Attention: x[64,197,768] -> qkv -> per-head attention (+rel pos bias) ->
// proj.
// GEMMs: fp16 tensor-core, 3-term Markidis split, operands pre-split in HBM.
//        256 thr, 8 warps (2x4), warp tile 64x32, term-major mma ordering.
// Attention: warp-per-4-q-rows, fp32, smem-resident K/V.
// ---------------------------------------------------------------------------

#define BATCH 64
#define NQ    197
#define CDIM  768
#define NH    12
#define HD    64
#define NP    196
#define MTOT  (BATCH * NQ)          // 12608

// fp32 scratch
__device__ float g_qkv[(size_t)MTOT * 3 * CDIM];
__device__ float g_attn[(size_t)MTOT * CDIM];

// pre-split fp16 planes
__device__ __half2 g_xhi[(size_t)MTOT * CDIM / 2];
__device__ __half2 g_xlo[(size_t)MTOT * CDIM / 2];
__device__ __half2 g_whi[(size_t)3 * CDIM * CDIM / 2];
__device__ __half2 g_wlo[(size_t)3 * CDIM * CDIM / 2];
__device__ __half2 g_phi[(size_t)CDIM * CDIM / 2];
__device__ __half2 g_plo[(size_t)CDIM * CDIM / 2];
__device__ __half2 g_ahi[(size_t)MTOT * CDIM / 2];
__device__ __half2 g_alo[(size_t)MTOT * CDIM / 2];

// ===========================================================================
// split: fp32 -> (hi, lo) fp16 planes.  hi = h(x), lo = h(x - f(hi)).
// ===========================================================================
__global__ void split_h(const float4* __restrict__ src, __half2* __restrict__ hi,
                        __half2* __restrict__ lo, int n4)
{
    int i = blockIdx.x * blockDim.x + threadIdx.x;
    if (i >= n4) return;
    float4 v = src[i];
    __half2 h0 = __floats2half2_rn(v.x, v.y);
    __half2 h1 = __floats2half2_rn(v.z, v.w);
    float2 f0 = __half22float2(h0);
    float2 f1 = __half22float2(h1);
    __half2 l0 = __floats2half2_rn(v.x - f0.x, v.y - f0.y);
    __half2 l1 = __floats2half2_rn(v.z - f1.x, v.w - f1.y);
    hi[2 * i]     = h0;
    hi[2 * i + 1] = h1;
    lo[2 * i]     = l0;
    lo[2 * i + 1] = l1;
}

// ===========================================================================
// fp16-split GEMM (NT): C[m][n] = sum_k A[m][k]*B[n][k] (+bias[n])
// BM=BN=128, BK=32, 256 threads = 8 warps (2 m-bands x 4 n-bands),
// warp tile 64x32.  ldmatrix + cp.async double buffer.
// ===========================================================================

__device__ __forceinline__ unsigned smem_u32(const void* p) {
    return (unsigned)__cvta_generic_to_shared(p);
}
__device__ __forceinline__ void cp_async16(unsigned dst, const void* src, bool pred) {
    int sz = pred ? 16 : 0;
    asm volatile("cp.async.cg.shared.global [%0], [%1], 16, %2;\n"
                 :: "r"(dst), "l"(src), "r"(sz));
}
__device__ __forceinline__ void cp_commit() { asm volatile("cp.async.commit_group;\n"); }
__device__ __forceinline__ void cp_wait0()  { asm volatile("cp.async.wait_group 0;\n"); }

__device__ __forceinline__ void ldsm_x4(uint32_t* r, unsigned a) {
    asm volatile("ldmatrix.sync.aligned.m8n8.x4.shared.b16 {%0,%1,%2,%3}, [%4];"
                 : "=r"(r[0]), "=r"(r[1]), "=r"(r[2]), "=r"(r[3]) : "r"(a));
}
__device__ __forceinline__ void ldsm_x2(uint32_t& r0, uint32_t& r1, unsigned a) {
    asm volatile("ldmatrix.sync.aligned.m8n8.x2.shared.b16 {%0,%1}, [%2];"
                 : "=r"(r0), "=r"(r1) : "r"(a));
}
__device__ __forceinline__ void mma_f16(float* d, const uint32_t* a, const uint32_t* b) {
    asm volatile(
        "mma.sync.aligned.m16n8k16.row.col.f32.f16.f16.f32 "
        "{%0,%1,%2,%3}, {%4,%5,%6,%7}, {%8,%9}, {%0,%1,%2,%3};"
        : "+f"(d[0]), "+f"(d[1]), "+f"(d[2]), "+f"(d[3])
        : "r"(a[0]), "r"(a[1]), "r"(a[2]), "r"(a[3]), "r"(b[0]), "r"(b[1]));
}

#define APAD   40                     // smem row stride (halfs): 32 + 8
#define PLANE  (128 * APAD)           // halfs per plane  (5120)
#define GBUFH  (2 * PLANE)            // halfs per buffer (hi+lo)
#define BBASE  (4 * PLANE)            // B region offset (halfs)
#define GSMEM  (8 * PLANE * 2)        // total bytes: 81920

__global__ __launch_bounds__(256, 2) void gemm_f16s(
    const __half* __restrict__ Ahi, const __half* __restrict__ Alo,
    const __half* __restrict__ Bhi, const __half* __restrict__ Blo,
    const float* __restrict__ bias, float* __restrict__ C,
    int M, int N, int K)
{
    extern __shared__ __half smg[];

    const int tid  = threadIdx.x;
    const int lane = tid & 31;
    const int wid  = tid >> 5;
    const int wm   = wid & 1;          // 64-row band
    const int wn   = wid >> 1;         // 32-col band (0..3)
    const int bm   = blockIdx.y * 128;
    const int bn   = blockIdx.x * 128;

    // loader: thread -> half a row (16 halfs = 32B) per plane
    const int lrow = tid >> 1;
    const int lcol = (tid & 1) * 16;
    const bool aok = (bm + lrow) < M;
    const __half* gA0 = Ahi + (size_t)(aok ? bm + lrow : 0) * K + lcol;
    const __half* gA1 = Alo + (size_t)(aok ? bm + lrow : 0) * K + lcol;
    const __half* gB0 = Bhi + (size_t)(bn + lrow) * K + lcol;
    const __half* gB1 = Blo + (size_t)(bn + lrow) * K + lcol;

    const unsigned a0Addr = smem_u32(smg) + (unsigned)(lrow * APAD + lcol) * 2u;
    const unsigned a1Addr = a0Addr + PLANE * 2;
    const unsigned b0Addr = a0Addr + BBASE * 2;
    const unsigned b1Addr = b0Addr + PLANE * 2;
    const unsigned BUFB   = GBUFH * 2;   // byte stride between buffers

    const int nIter = K / 32;

    float acc[4][4][4];
#pragma unroll
    for (int i = 0; i < 4; i++)
#pragma unroll
        for (int j = 0; j < 4; j++)
#pragma unroll
            for (int r = 0; r < 4; r++) acc[i][j][r] = 0.f;

    // prologue
    {
        cp_async16(a0Addr,      gA0,     aok);
        cp_async16(a0Addr + 16, gA0 + 8, aok);
        cp_async16(a1Addr,      gA1,     aok);
        cp_async16(a1Addr + 16, gA1 + 8, aok);
        cp_async16(b0Addr,      gB0,     true);
        cp_async16(b0Addr + 16, gB0 + 8, true);
        cp_async16(b1Addr,      gB1,     true);
        cp_async16(b1Addr + 16, gB1 + 8, true);
        cp_commit();
    }

    for (int it = 0; it < nIter; it++) {
        cp_wait0();
        __syncthreads();

        if (it + 1 < nIter) {
            const int k0 = (it + 1) * 32;
            const unsigned off = (unsigned)((it + 1) & 1) * BUFB;
            cp_async16(a0Addr + off,      gA0 + k0,     aok);
            cp_async16(a0Addr + off + 16, gA0 + k0 + 8, aok);
            cp_async16(a1Addr + off,      gA1 + k0,     aok);
            cp_async16(a1Addr + off + 16, gA1 + k0 + 8, aok);
            cp_async16(b0Addr + off,      gB0 + k0,     true);
            cp_async16(b0Addr + off + 16, gB0 + k0 + 8, true);
            cp_async16(b1Addr + off,      gB1 + k0,     true);
            cp_async16(b1Addr + off + 16, gB1 + k0 + 8, true);
            cp_commit();
        }

        const __half* sa0 = smg + (it & 1) * GBUFH;
        const __half* sa1 = sa0 + PLANE;
        const __half* sb0 = smg + BBASE + (it & 1) * GBUFH;
        const __half* sb1 = sb0 + PLANE;

#pragma unroll
        for (int ks = 0; ks < 2; ks++) {
            // B fragments: 4 nt x 2 planes
            uint32_t bh[4][2], bl[4][2];
#pragma unroll
            for (int nt = 0; nt < 4; nt++) {
                const int row = wn * 32 + nt * 8 + (lane & 7);
                const int col = ks * 16 + ((lane >> 3) & 1) * 8;
                ldsm_x2(bh[nt][0], bh[nt][1], smem_u32(sb0 + row * APAD + col));
                ldsm_x2(bl[nt][0], bl[nt][1], smem_u32(sb1 + row * APAD + col));
            }
#pragma unroll
            for (int mt = 0; mt < 4; mt++) {
                const int row = wm * 64 + mt * 16 + (lane & 15);
                const int col = ks * 16 + (lane >> 4) * 8;
                uint32_t ah[4], al[4];
                ldsm_x4(ah, smem_u32(sa0 + row * APAD + col));
                ldsm_x4(al, smem_u32(sa1 + row * APAD + col));
                // term-major: consecutive mmas hit different accumulators
#pragma unroll
                for (int nt = 0; nt < 4; nt++) mma_f16(acc[mt][nt], ah, bh[nt]);
#pragma unroll
                for (int nt = 0; nt < 4; nt++) mma_f16(acc[mt][nt], al, bh[nt]);
#pragma unroll
                for (int nt = 0; nt < 4; nt++) mma_f16(acc[mt][nt], ah, bl[nt]);
            }
        }
    }

    // epilogue
    const int g = lane >> 2;
    const int t = lane & 3;
#pragma unroll
    for (int mt = 0; mt < 4; mt++) {
        const int r0 = bm + wm * 64 + mt * 16 + g;
#pragma unroll
        for (int nt = 0; nt < 4; nt++) {
            const int col = bn + wn * 32 + nt * 8 + 2 * t;
            const float bv0 = bias ? bias[col]     : 0.f;
            const float bv1 = bias ? bias[col + 1] : 0.f;
            if (r0 < M) {
                float2 v = make_float2(acc[mt][nt][0] + bv0, acc[mt][nt][1] + bv1);
                *(float2*)&C[(size_t)r0 * N + col] = v;
            }
            if (r0 + 8 < M) {
                float2 v = make_float2(acc[mt][nt][2] + bv0, acc[mt][nt][3] + bv1);
                *(float2*)&C[(size_t)(r0 + 8) * N + col] = v;
            }
        }
    }
}

// ===========================================================================
// Attention: block per (b,h), 512 threads = 16 warps, warp-per-4-q-rows.
// ===========================================================================
#define AT_THREADS 512
#define AT_WARPS   16
#define QPW        4
#define NGRP       50       // ceil(197/4)
#define KROWS      224
#define RS         17
#define PBS        224

__global__ __launch_bounds__(AT_THREADS) void attn_warp(
    const float* __restrict__ qkv, const float* __restrict__ rpb_table,
    const int* __restrict__ rel_idx, float* __restrict__ out)
{
    extern __shared__ float4 sm4[];
    float4* K4     = sm4;                               // [KROWS][RS]
    float4* V4     = K4 + KROWS * RS;                   // [KROWS][RS]
    float4* QB     = V4 + KROWS * RS;                   // [AT_WARPS][QPW][RS]
    float*  bias_s = (float*)(QB + AT_WARPS * QPW * RS); // 736
    float*  pbuf   = bias_s + 736;                      // [AT_WARPS][QPW][PBS]

    const int tid  = threadIdx.x;
    const int lane = tid & 31;
    const int wid  = tid >> 5;
    const int b = blockIdx.x / NH;
    const int h = blockIdx.x % NH;

    const float* kbase = qkv + (size_t)b * NQ * (3 * CDIM) + CDIM + h * HD;
    const float* vbase = kbase + CDIM;
    const float* qbase = qkv + (size_t)b * NQ * (3 * CDIM) + h * HD;
    float* obase = out + (size_t)b * NQ * CDIM + h * HD;

    for (int i = tid; i < NQ * 16; i += AT_THREADS) {
        int n = i >> 4, d4 = i & 15;
        K4[n * RS + d4] = ((const float4*)(kbase + (size_t)n * (3 * CDIM)))[d4];
        V4[n * RS + d4] = ((const float4*)(vbase + (size_t)n * (3 * CDIM)))[d4];
    }
    for (int i = tid; i < 729; i += AT_THREADS) bias_s[i] = rpb_table[i * NH + h];
    __syncthreads();

    for (int p = wid; p < NGRP; p += AT_WARPS) {
        const int q0 = QPW * p;

        // load scaled q rows (clamped) into per-warp smem: 2 passes x 2 rows
        {
            const int d4 = lane & 15;
#pragma unroll
            for (int r2 = 0; r2 < 2; r2++) {
                const int r  = (lane >> 4) + 2 * r2;
                int qq = q0 + r; if (qq > NQ - 1) qq = NQ - 1;
                float4 v = ((const float4*)(qbase + (size_t)qq * (3 * CDIM)))[d4];
                v.x *= 0.125f; v.y *= 0.125f; v.z *= 0.125f; v.w *= 0.125f;
                QB[(wid * QPW + r) * RS + d4] = v;
            }
        }
        __syncwarp();

        float s[QPW][7];
#pragma unroll
        for (int r = 0; r < QPW; r++)
#pragma unroll
            for (int c = 0; c < 7; c++) s[r][c] = 0.f;

#pragma unroll
        for (int d4 = 0; d4 < 16; d4++) {
            float4 qv[QPW];
#pragma unroll
            for (int r = 0; r < QPW; r++) qv[r] = QB[(wid * QPW + r) * RS + d4];
#pragma unroll
            for (int c = 0; c < 7; c++) {
                const int j = lane + 32 * c;
                const float4 kv = K4[j * RS + d4];
#pragma unroll
                for (int r = 0; r < QPW; r++) {
                    s[r][c] += qv[r].x * kv.x + qv[r].y * kv.y
                             + qv[r].z * kv.z + qv[r].w * kv.w;
                }
            }
        }

        // bias + mask
#pragma unroll
        for (int c = 0; c < 7; c++) {
            const int j = lane + 32 * c;
            if (j < NQ) {
                if (j > 0) {
#pragma unroll
                    for (int r = 0; r < QPW; r++) {
                        const int qr = q0 + r;
                        if (qr > 0 && qr < NQ)
                            s[r][c] += bias_s[rel_idx[(qr - 1) * NP + (j - 1)]];
                    }
                }
            } else {
#pragma unroll
                for (int r = 0; r < QPW; r++) s[r][c] = -CUDART_INF_F;
            }
        }

        // softmax per row
        float mx[QPW], tot[QPW];
#pragma unroll
        for (int r = 0; r < QPW; r++) {
            float m = s[r][0];
#pragma unroll
            for (int c = 1; c < 7; c++) m = fmaxf(m, s[r][c]);
            mx[r] = m;
        }
#pragma unroll
        for (int o = 16; o > 0; o >>= 1)
#pragma unroll
            for (int r = 0; r < QPW; r++)
                mx[r] = fmaxf(mx[r], __shfl_xor_sync(0xffffffffu, mx[r], o));
#pragma unroll
        for (int r = 0; r < QPW; r++) {
            float t = 0.f;
#pragma unroll
            for (int c = 0; c < 7; c++) { s[r][c] = __expf(s[r][c] - mx[r]); t += s[r][c]; }
            tot[r] = t;
        }
#pragma unroll
        for (int o = 16; o > 0; o >>= 1)
#pragma unroll
            for (int r = 0; r < QPW; r++)
                tot[r] += __shfl_xor_sync(0xffffffffu, tot[r], o);
#pragma unroll
        for (int r = 0; r < QPW; r++) {
            const float inv = 1.f / tot[r];
#pragma unroll
            for (int c = 0; c < 7; c++) {
                const int j = lane + 32 * c;
                if (j < NQ) pbuf[(wid * QPW + r) * PBS + j] = s[r][c] * inv;
            }
        }
        __syncwarp();

        // PV: lane -> d4 = lane&15, key parity = lane>>4
        {
            const int d4 = lane & 15;
            const int cc = lane >> 4;
            float4 a[QPW];
#pragma unroll
            for (int r = 0; r < QPW; r++) a[r] = make_float4(0.f, 0.f, 0.f, 0.f);
            for (int j = cc; j < NQ; j += 2) {
                const float4 v = V4[j * RS + d4];
#pragma unroll
                for (int r = 0; r < QPW; r++) {
                    const float pr = pbuf[(wid * QPW + r) * PBS + j];
                    a[r].x += pr * v.x; a[r].y += pr * v.y;
                    a[r].z += pr * v.z; a[r].w += pr * v.w;
                }
            }
#pragma unroll
            for (int r = 0; r < QPW; r++) {
                a[r].x += __shfl_xor_sync(0xffffffffu, a[r].x, 16);
                a[r].y += __shfl_xor_sync(0xffffffffu, a[r].y, 16);
                a[r].z += __shfl_xor_sync(0xffffffffu, a[r].z, 16);
                a[r].w += __shfl_xor_sync(0xffffffffu, a[r].w, 16);
            }
            // lanes<16 store rows 0,1; lanes>=16 store rows 2,3
            const int rbase = (lane < 16) ? 0 : 2;
#pragma unroll
            for (int rr = 0; rr < 2; rr++) {
                const int r = rbase + rr;
                const int qr = q0 + r;
                if (qr < NQ)
                    ((float4*)(obase + (size_t)qr * CDIM))[d4] = a[r];
            }
        }
        __syncwarp();
    }
}

// ===========================================================================
extern "C" void kernel_launch(void* const* d_in, const int* in_sizes, int n_in,
                              void* d_out, int out_size)
{
    const float* x      = (const float*)d_in[0];
    const float* w_qkv  = (const float*)d_in[1];
    const float* w_proj = (const float*)d_in[2];
    const float* b_proj = (const float*)d_in[3];
    const float* rpb    = (const float*)d_in[4];
    const int*   relidx = (const int*)d_in[5];
    float* out = (float*)d_out;

    float *qkv_s, *attn_s;
    __half2 *xhi, *xlo, *whi, *wlo, *phi, *plo, *ahi, *alo;
    cudaGetSymbolAddress((void**)&qkv_s, g_qkv);
    cudaGetSymbolAddress((void**)&attn_s, g_attn);
    cudaGetSymbolAddress((void**)&xhi, g_xhi);
    cudaGetSymbolAddress((void**)&xlo, g_xlo);
    cudaGetSymbolAddress((void**)&whi, g_whi);
    cudaGetSymbolAddress((void**)&wlo, g_wlo);
    cudaGetSymbolAddress((void**)&phi, g_phi);
    cudaGetSymbolAddress((void**)&plo, g_plo);
    cudaGetSymbolAddress((void**)&ahi, g_ahi);
    cudaGetSymbolAddress((void**)&alo, g_alo);

    const int M = MTOT;   // 12608

    // 0) pre-split x, w_qkv, w_proj
    {
        int n4 = M * CDIM / 4;
        split_h<<<(n4 + 255) / 256, 256>>>((const float4*)x, xhi, xlo, n4);
        n4 = 3 * CDIM * CDIM / 4;
        split_h<<<(n4 + 255) / 256, 256>>>((const float4*)w_qkv, whi, wlo, n4);
        n4 = CDIM * CDIM / 4;
        split_h<<<(n4 + 255) / 256, 256>>>((const float4*)w_proj, phi, plo, n4);
    }

    cudaFuncSetAttribute(gemm_f16s, cudaFuncAttributeMaxDynamicSharedMemorySize, GSMEM);

    // 1) QKV GEMM
    {
        dim3 grid((3 * CDIM) / 128, (M + 127) / 128);
        gemm_f16s<<<grid, 256, GSMEM>>>((const __half*)xhi, (const __half*)xlo,
                                        (const __half*)whi, (const __half*)wlo,
                                        nullptr, qkv_s, M, 3 * CDIM, CDIM);
    }

    // 2) attention
    {
        size_t smem = (size_t)(KROWS * RS * 2 + AT_WARPS * QPW * RS) * sizeof(float4)
                    + (size_t)(736 + AT_WARPS * QPW * PBS) * sizeof(float);
        cudaFuncSetAttribute(attn_warp, cudaFuncAttributeMaxDynamicSharedMemorySize,
                             (int)smem);
        attn_warp<<<BATCH * NH, AT_THREADS, smem>>>(qkv_s, rpb, relidx, attn_s);
    }

    // 3) split attention output, then proj GEMM
    {
        int n4 = M * CDIM / 4;
        split_h<<<(n4 + 255) / 256, 256>>>((const float4*)attn_s, ahi, alo, n4);
        dim3 grid(CDIM / 128, (M + 127) / 128);
        gemm_f16s<<<grid, 256, GSMEM>>>((const __half*)ahi, (const __half*)alo,
                                        (const __half*)phi, (const __half*)plo,
                                        b_proj, out, M, CDIM, CDIM);
    }
}

// round 8
// speedup vs baseline: 3.6386x; 1.2061x over previous
#include <cuda_runtime.h>
#include <cuda_fp16.h>
#include <math_constants.h>
#include <cstdint>

// ---------------------------------------------------------------------------
// RPE_Attention: x[64,197,768] -> qkv -> per-head attention (+rel pos bias) ->
// proj.
// GEMMs: fp16 mma.sync 3-term Markidis split (R6 proven config).
// Attention: NEW — tensorized with mma.sync, 3-term split QK^T and PV,
//            register-resident softmax, P remapped accum->A-fragment.
// ---------------------------------------------------------------------------

#define BATCH 64
#define NQ    197
#define CDIM  768
#define NH    12
#define HD    64
#define NP    196
#define MTOT  (BATCH * NQ)          // 12608

// fp32 scratch
__device__ float g_qkv[(size_t)MTOT * 3 * CDIM];
__device__ float g_attn[(size_t)MTOT * CDIM];

// pre-split fp16 planes for GEMMs
__device__ __half2 g_xhi[(size_t)MTOT * CDIM / 2];
__device__ __half2 g_xlo[(size_t)MTOT * CDIM / 2];
__device__ __half2 g_whi[(size_t)3 * CDIM * CDIM / 2];
__device__ __half2 g_wlo[(size_t)3 * CDIM * CDIM / 2];
__device__ __half2 g_phi[(size_t)CDIM * CDIM / 2];
__device__ __half2 g_plo[(size_t)CDIM * CDIM / 2];
__device__ __half2 g_ahi[(size_t)MTOT * CDIM / 2];
__device__ __half2 g_alo[(size_t)MTOT * CDIM / 2];

// ===========================================================================
// common helpers
// ===========================================================================
__device__ __forceinline__ unsigned smem_u32(const void* p) {
    return (unsigned)__cvta_generic_to_shared(p);
}
__device__ __forceinline__ void cp_async16(unsigned dst, const void* src, bool pred) {
    int sz = pred ? 16 : 0;
    asm volatile("cp.async.cg.shared.global [%0], [%1], 16, %2;\n"
                 :: "r"(dst), "l"(src), "r"(sz));
}
__device__ __forceinline__ void cp_commit() { asm volatile("cp.async.commit_group;\n"); }
__device__ __forceinline__ void cp_wait0()  { asm volatile("cp.async.wait_group 0;\n"); }

__device__ __forceinline__ void ldsm_x4(uint32_t* r, unsigned a) {
    asm volatile("ldmatrix.sync.aligned.m8n8.x4.shared.b16 {%0,%1,%2,%3}, [%4];"
                 : "=r"(r[0]), "=r"(r[1]), "=r"(r[2]), "=r"(r[3]) : "r"(a));
}
__device__ __forceinline__ void ldsm_x2(uint32_t& r0, uint32_t& r1, unsigned a) {
    asm volatile("ldmatrix.sync.aligned.m8n8.x2.shared.b16 {%0,%1}, [%2];"
                 : "=r"(r0), "=r"(r1) : "r"(a));
}
__device__ __forceinline__ void mma_f16(float* d, const uint32_t* a, const uint32_t* b) {
    asm volatile(
        "mma.sync.aligned.m16n8k16.row.col.f32.f16.f16.f32 "
        "{%0,%1,%2,%3}, {%4,%5,%6,%7}, {%8,%9}, {%0,%1,%2,%3};"
        : "+f"(d[0]), "+f"(d[1]), "+f"(d[2]), "+f"(d[3])
        : "r"(a[0]), "r"(a[1]), "r"(a[2]), "r"(a[3]), "r"(b[0]), "r"(b[1]));
}

// ===========================================================================
// split: fp32 -> (hi, lo) fp16 planes.
// ===========================================================================
__global__ void split_h(const float4* __restrict__ src, __half2* __restrict__ hi,
                        __half2* __restrict__ lo, int n4)
{
    int i = blockIdx.x * blockDim.x + threadIdx.x;
    if (i >= n4) return;
    float4 v = src[i];
    __half2 h0 = __floats2half2_rn(v.x, v.y);
    __half2 h1 = __floats2half2_rn(v.z, v.w);
    float2 f0 = __half22float2(h0);
    float2 f1 = __half22float2(h1);
    __half2 l0 = __floats2half2_rn(v.x - f0.x, v.y - f0.y);
    __half2 l1 = __floats2half2_rn(v.z - f1.x, v.w - f1.y);
    hi[2 * i]     = h0;
    hi[2 * i + 1] = h1;
    lo[2 * i]     = l0;
    lo[2 * i + 1] = l1;
}

// ===========================================================================
// fp16-split GEMM (NT) — unchanged from R6 (proven).
// ===========================================================================
#define APAD   40
#define PLANE  (128 * APAD)
#define GBUFH  (2 * PLANE)
#define BBASE  (4 * PLANE)
#define GSMEM  (8 * PLANE * 2)

__global__ __launch_bounds__(256, 2) void gemm_f16s(
    const __half* __restrict__ Ahi, const __half* __restrict__ Alo,
    const __half* __restrict__ Bhi, const __half* __restrict__ Blo,
    const float* __restrict__ bias, float* __restrict__ C,
    int M, int N, int K)
{
    extern __shared__ __half smg[];

    const int tid  = threadIdx.x;
    const int lane = tid & 31;
    const int wid  = tid >> 5;
    const int wm   = wid & 1;
    const int wn   = wid >> 1;
    const int bm   = blockIdx.y * 128;
    const int bn   = blockIdx.x * 128;

    const int lrow = tid >> 1;
    const int lcol = (tid & 1) * 16;
    const bool aok = (bm + lrow) < M;
    const __half* gA0 = Ahi + (size_t)(aok ? bm + lrow : 0) * K + lcol;
    const __half* gA1 = Alo + (size_t)(aok ? bm + lrow : 0) * K + lcol;
    const __half* gB0 = Bhi + (size_t)(bn + lrow) * K + lcol;
    const __half* gB1 = Blo + (size_t)(bn + lrow) * K + lcol;

    const unsigned a0Addr = smem_u32(smg) + (unsigned)(lrow * APAD + lcol) * 2u;
    const unsigned a1Addr = a0Addr + PLANE * 2;
    const unsigned b0Addr = a0Addr + BBASE * 2;
    const unsigned b1Addr = b0Addr + PLANE * 2;
    const unsigned BUFB   = GBUFH * 2;

    const int nIter = K / 32;

    float acc[4][4][4];
#pragma unroll
    for (int i = 0; i < 4; i++)
#pragma unroll
        for (int j = 0; j < 4; j++)
#pragma unroll
            for (int r = 0; r < 4; r++) acc[i][j][r] = 0.f;

    {
        cp_async16(a0Addr,      gA0,     aok);
        cp_async16(a0Addr + 16, gA0 + 8, aok);
        cp_async16(a1Addr,      gA1,     aok);
        cp_async16(a1Addr + 16, gA1 + 8, aok);
        cp_async16(b0Addr,      gB0,     true);
        cp_async16(b0Addr + 16, gB0 + 8, true);
        cp_async16(b1Addr,      gB1,     true);
        cp_async16(b1Addr + 16, gB1 + 8, true);
        cp_commit();
    }

    for (int it = 0; it < nIter; it++) {
        cp_wait0();
        __syncthreads();

        if (it + 1 < nIter) {
            const int k0 = (it + 1) * 32;
            const unsigned off = (unsigned)((it + 1) & 1) * BUFB;
            cp_async16(a0Addr + off,      gA0 + k0,     aok);
            cp_async16(a0Addr + off + 16, gA0 + k0 + 8, aok);
            cp_async16(a1Addr + off,      gA1 + k0,     aok);
            cp_async16(a1Addr + off + 16, gA1 + k0 + 8, aok);
            cp_async16(b0Addr + off,      gB0 + k0,     true);
            cp_async16(b0Addr + off + 16, gB0 + k0 + 8, true);
            cp_async16(b1Addr + off,      gB1 + k0,     true);
            cp_async16(b1Addr + off + 16, gB1 + k0 + 8, true);
            cp_commit();
        }

        const __half* sa0 = smg + (it & 1) * GBUFH;
        const __half* sa1 = sa0 + PLANE;
        const __half* sb0 = smg + BBASE + (it & 1) * GBUFH;
        const __half* sb1 = sb0 + PLANE;

#pragma unroll
        for (int ks = 0; ks < 2; ks++) {
            uint32_t bh[4][2], bl[4][2];
#pragma unroll
            for (int nt = 0; nt < 4; nt++) {
                const int row = wn * 32 + nt * 8 + (lane & 7);
                const int col = ks * 16 + ((lane >> 3) & 1) * 8;
                ldsm_x2(bh[nt][0], bh[nt][1], smem_u32(sb0 + row * APAD + col));
                ldsm_x2(bl[nt][0], bl[nt][1], smem_u32(sb1 + row * APAD + col));
            }
#pragma unroll
            for (int mt = 0; mt < 4; mt++) {
                const int row = wm * 64 + mt * 16 + (lane & 15);
                const int col = ks * 16 + (lane >> 4) * 8;
                uint32_t ah[4], al[4];
                ldsm_x4(ah, smem_u32(sa0 + row * APAD + col));
                ldsm_x4(al, smem_u32(sa1 + row * APAD + col));
#pragma unroll
                for (int nt = 0; nt < 4; nt++) mma_f16(acc[mt][nt], ah, bh[nt]);
#pragma unroll
                for (int nt = 0; nt < 4; nt++) mma_f16(acc[mt][nt], al, bh[nt]);
#pragma unroll
                for (int nt = 0; nt < 4; nt++) mma_f16(acc[mt][nt], ah, bl[nt]);
            }
        }
    }

    const int g = lane >> 2;
    const int t = lane & 3;
#pragma unroll
    for (int mt = 0; mt < 4; mt++) {
        const int r0 = bm + wm * 64 + mt * 16 + g;
#pragma unroll
        for (int nt = 0; nt < 4; nt++) {
            const int col = bn + wn * 32 + nt * 8 + 2 * t;
            const float bv0 = bias ? bias[col]     : 0.f;
            const float bv1 = bias ? bias[col + 1] : 0.f;
            if (r0 < M) {
                float2 v = make_float2(acc[mt][nt][0] + bv0, acc[mt][nt][1] + bv1);
                *(float2*)&C[(size_t)r0 * N + col] = v;
            }
            if (r0 + 8 < M) {
                float2 v = make_float2(acc[mt][nt][2] + bv0, acc[mt][nt][3] + bv1);
                *(float2*)&C[(size_t)(r0 + 8) * N + col] = v;
            }
        }
    }
}

// ===========================================================================
// Tensorized attention: block per (b,h), 256 threads = 8 warps.
// Q,K split hi/lo [208 x 64] (stride 72 halfs); V^T split hi/lo [64 x 208]
// (stride 232 halfs).  Warp owns m-tiles of 16 q rows (13 tiles).
// S = 3-term split mma;  softmax in registers;  P re-split in regs;
// O = 3-term split mma;  fp32 stores.
// ===========================================================================
#define NPAD   208
#define QKS    72
#define VTS    232
#define QH_OFF 0
#define QL_OFF (NPAD * QKS)            // 14976
#define KH_OFF (2 * NPAD * QKS)
#define KL_OFF (3 * NPAD * QKS)
#define VTH_OFF (4 * NPAD * QKS)       // 59904
#define VTL_OFF (VTH_OFF + HD * VTS)   // 74752
#define ATM_HALFS (VTL_OFF + HD * VTS) // 89600
#define ATM_SMEM  (ATM_HALFS * 2 + 736 * 4)   // 182144 bytes

__device__ __forceinline__ void pack2(float x, float y, uint32_t& hi, uint32_t& lo) {
    __half2 h = __floats2half2_rn(x, y);
    float2 f = __half22float2(h);
    __half2 l = __floats2half2_rn(x - f.x, y - f.y);
    hi = *reinterpret_cast<uint32_t*>(&h);
    lo = *reinterpret_cast<uint32_t*>(&l);
}

__global__ __launch_bounds__(256, 1) void attn_mma(
    const float* __restrict__ qkv, const float* __restrict__ rpb_table,
    const int* __restrict__ rel_idx, float* __restrict__ out)
{
    extern __shared__ __align__(16) __half sma[];
    __half* QH  = sma + QH_OFF;
    __half* QL  = sma + QL_OFF;
    __half* KH  = sma + KH_OFF;
    __half* KL  = sma + KL_OFF;
    __half* VTH = sma + VTH_OFF;
    __half* VTL = sma + VTL_OFF;
    float*  bias_s = (float*)(sma + ATM_HALFS);

    const int tid  = threadIdx.x;
    const int lane = tid & 31;
    const int wid  = tid >> 5;
    const int b = blockIdx.x / NH;
    const int h = blockIdx.x % NH;

    // ---- load + split Q(scaled), K, V^T ----
    const float* base0 = qkv + (size_t)b * NQ * (3 * CDIM) + h * HD;
    for (int i = tid; i < NPAD * HD; i += 256) {
        const int n = i >> 6, d = i & 63;
        float qv = 0.f, kv = 0.f, vv = 0.f;
        if (n < NQ) {
            const float* p = base0 + (size_t)n * (3 * CDIM) + d;
            qv = p[0] * 0.125f;
            kv = p[CDIM];
            vv = p[2 * CDIM];
        }
        __half qh_ = __float2half_rn(qv);
        QH[n * QKS + d] = qh_;
        QL[n * QKS + d] = __float2half_rn(qv - __half2float(qh_));
        __half kh_ = __float2half_rn(kv);
        KH[n * QKS + d] = kh_;
        KL[n * QKS + d] = __float2half_rn(kv - __half2float(kh_));
        __half vh_ = __float2half_rn(vv);
        VTH[d * VTS + n] = vh_;
        VTL[d * VTS + n] = __float2half_rn(vv - __half2float(vh_));
    }
    for (int i = tid; i < 729; i += 256) bias_s[i] = rpb_table[i * NH + h];
    __syncthreads();

    const int g = lane >> 2;
    const int t = lane & 3;
    const int idx = lane >> 3;          // ldsm_x4 address group

    for (int mt = wid; mt < 13; mt += 8) {
        const int q0 = mt * 16;

        // Q A-fragments (4 k-chunks of 16)
        uint32_t qfh[4][4], qfl[4][4];
        {
            const int row = q0 + (lane & 15);
            const int col = (lane >> 4) * 8;
#pragma unroll
            for (int kt = 0; kt < 4; kt++) {
                ldsm_x4(qfh[kt], smem_u32(QH + row * QKS + kt * 16 + col));
                ldsm_x4(qfl[kt], smem_u32(QL + row * QKS + kt * 16 + col));
            }
        }

        // ---- scores: S[16 x 208] ----
        float sc[26][4];
#pragma unroll
        for (int nt = 0; nt < 26; nt++)
#pragma unroll
            for (int e = 0; e < 4; e++) sc[nt][e] = 0.f;

#pragma unroll
        for (int ntp = 0; ntp < 13; ntp++) {
            const int row = ntp * 16 + (idx >> 1) * 8 + (lane & 7);
            const int col = (idx & 1) * 8;
            uint32_t kf[4][4], lf[4][4];
#pragma unroll
            for (int kt = 0; kt < 4; kt++) {
                ldsm_x4(kf[kt], smem_u32(KH + row * QKS + kt * 16 + col));
                ldsm_x4(lf[kt], smem_u32(KL + row * QKS + kt * 16 + col));
            }
#pragma unroll
            for (int kt = 0; kt < 4; kt++) {
                mma_f16(sc[2 * ntp],     qfh[kt], &kf[kt][0]);
                mma_f16(sc[2 * ntp + 1], qfh[kt], &kf[kt][2]);
                mma_f16(sc[2 * ntp],     qfl[kt], &kf[kt][0]);
                mma_f16(sc[2 * ntp + 1], qfl[kt], &kf[kt][2]);
                mma_f16(sc[2 * ntp],     qfh[kt], &lf[kt][0]);
                mma_f16(sc[2 * ntp + 1], qfh[kt], &lf[kt][2]);
            }
        }

        // ---- bias + mask ----
        const int qa = q0 + g;
        const int qb = q0 + g + 8;
        const bool va = qa < NQ;
        const bool vb = qb < NQ;
#pragma unroll
        for (int nt = 0; nt < 26; nt++) {
            const int j0 = nt * 8 + 2 * t;
            const int j1 = j0 + 1;
            // c0:(qa,j0) c1:(qa,j1) c2:(qb,j0) c3:(qb,j1)
            {
                float s = sc[nt][0];
                if (!va) s = 0.f;
                else if (j0 >= NQ) s = -CUDART_INF_F;
                else if (qa > 0 && j0 > 0)
                    s += bias_s[__ldg(rel_idx + (qa - 1) * NP + (j0 - 1))];
                sc[nt][0] = s;
            }
            {
                float s = sc[nt][1];
                if (!va) s = 0.f;
                else if (j1 >= NQ) s = -CUDART_INF_F;
                else if (qa > 0)
                    s += bias_s[__ldg(rel_idx + (qa - 1) * NP + (j1 - 1))];
                sc[nt][1] = s;
            }
            {
                float s = sc[nt][2];
                if (!vb) s = 0.f;
                else if (j0 >= NQ) s = -CUDART_INF_F;
                else if (qb > 0 && j0 > 0)
                    s += bias_s[__ldg(rel_idx + (qb - 1) * NP + (j0 - 1))];
                sc[nt][2] = s;
            }
            {
                float s = sc[nt][3];
                if (!vb) s = 0.f;
                else if (j1 >= NQ) s = -CUDART_INF_F;
                else if (qb > 0)
                    s += bias_s[__ldg(rel_idx + (qb - 1) * NP + (j1 - 1))];
                sc[nt][3] = s;
            }
        }

        // ---- softmax (rows qa, qb live on lane group {4g..4g+3}) ----
        float mA = -CUDART_INF_F, mB = -CUDART_INF_F;
#pragma unroll
        for (int nt = 0; nt < 26; nt++) {
            mA = fmaxf(mA, fmaxf(sc[nt][0], sc[nt][1]));
            mB = fmaxf(mB, fmaxf(sc[nt][2], sc[nt][3]));
        }
        mA = fmaxf(mA, __shfl_xor_sync(0xffffffffu, mA, 1));
        mA = fmaxf(mA, __shfl_xor_sync(0xffffffffu, mA, 2));
        mB = fmaxf(mB, __shfl_xor_sync(0xffffffffu, mB, 1));
        mB = fmaxf(mB, __shfl_xor_sync(0xffffffffu, mB, 2));

        float eA = 0.f, eB = 0.f;
#pragma unroll
        for (int nt = 0; nt < 26; nt++) {
            sc[nt][0] = __expf(sc[nt][0] - mA);
            sc[nt][1] = __expf(sc[nt][1] - mA);
            sc[nt][2] = __expf(sc[nt][2] - mB);
            sc[nt][3] = __expf(sc[nt][3] - mB);
            eA += sc[nt][0] + sc[nt][1];
            eB += sc[nt][2] + sc[nt][3];
        }
        eA += __shfl_xor_sync(0xffffffffu, eA, 1);
        eA += __shfl_xor_sync(0xffffffffu, eA, 2);
        eB += __shfl_xor_sync(0xffffffffu, eB, 1);
        eB += __shfl_xor_sync(0xffffffffu, eB, 2);
        const float invA = 1.f / eA;
        const float invB = 1.f / eB;

        // ---- P -> split fp16 A-fragments ----
        uint32_t ph[13][4], pl[13][4];
#pragma unroll
        for (int kt = 0; kt < 13; kt++) {
            pack2(sc[2 * kt][0] * invA,     sc[2 * kt][1] * invA,     ph[kt][0], pl[kt][0]);
            pack2(sc[2 * kt][2] * invB,     sc[2 * kt][3] * invB,     ph[kt][1], pl[kt][1]);
            pack2(sc[2 * kt + 1][0] * invA, sc[2 * kt + 1][1] * invA, ph[kt][2], pl[kt][2]);
            pack2(sc[2 * kt + 1][2] * invB, sc[2 * kt + 1][3] * invB, ph[kt][3], pl[kt][3]);
        }

        // ---- PV: O[16 x 64] ----
        float oc[8][4];
#pragma unroll
        for (int dt = 0; dt < 8; dt++)
#pragma unroll
            for (int e = 0; e < 4; e++) oc[dt][e] = 0.f;

#pragma unroll
        for (int dtp = 0; dtp < 4; dtp++) {
            const int vrow = dtp * 16 + (idx >> 1) * 8 + (lane & 7);
            const int vcol = (idx & 1) * 8;
#pragma unroll
            for (int kt = 0; kt < 13; kt++) {
                uint32_t vh[4], vl[4];
                ldsm_x4(vh, smem_u32(VTH + vrow * VTS + kt * 16 + vcol));
                ldsm_x4(vl, smem_u32(VTL + vrow * VTS + kt * 16 + vcol));
                mma_f16(oc[2 * dtp],     ph[kt], &vh[0]);
                mma_f16(oc[2 * dtp + 1], ph[kt], &vh[2]);
                mma_f16(oc[2 * dtp],     pl[kt], &vh[0]);
                mma_f16(oc[2 * dtp + 1], pl[kt], &vh[2]);
                mma_f16(oc[2 * dtp],     ph[kt], &vl[0]);
                mma_f16(oc[2 * dtp + 1], ph[kt], &vl[2]);
            }
        }

        // ---- store ----
        float* ob = out + (size_t)b * NQ * CDIM + h * HD;
#pragma unroll
        for (int dt = 0; dt < 8; dt++) {
            const int d0 = dt * 8 + 2 * t;
            if (va) *(float2*)&ob[(size_t)qa * CDIM + d0] = make_float2(oc[dt][0], oc[dt][1]);
            if (vb) *(float2*)&ob[(size_t)qb * CDIM + d0] = make_float2(oc[dt][2], oc[dt][3]);
        }
    }
}

// ===========================================================================
extern "C" void kernel_launch(void* const* d_in, const int* in_sizes, int n_in,
                              void* d_out, int out_size)
{
    const float* x      = (const float*)d_in[0];
    const float* w_qkv  = (const float*)d_in[1];
    const float* w_proj = (const float*)d_in[2];
    const float* b_proj = (const float*)d_in[3];
    const float* rpb    = (const float*)d_in[4];
    const int*   relidx = (const int*)d_in[5];
    float* out = (float*)d_out;

    float *qkv_s, *attn_s;
    __half2 *xhi, *xlo, *whi, *wlo, *phi, *plo, *ahi, *alo;
    cudaGetSymbolAddress((void**)&qkv_s, g_qkv);
    cudaGetSymbolAddress((void**)&attn_s, g_attn);
    cudaGetSymbolAddress((void**)&xhi, g_xhi);
    cudaGetSymbolAddress((void**)&xlo, g_xlo);
    cudaGetSymbolAddress((void**)&whi, g_whi);
    cudaGetSymbolAddress((void**)&wlo, g_wlo);
    cudaGetSymbolAddress((void**)&phi, g_phi);
    cudaGetSymbolAddress((void**)&plo, g_plo);
    cudaGetSymbolAddress((void**)&ahi, g_ahi);
    cudaGetSymbolAddress((void**)&alo, g_alo);

    const int M = MTOT;   // 12608

    // 0) pre-split x, w_qkv, w_proj
    {
        int n4 = M * CDIM / 4;
        split_h<<<(n4 + 255) / 256, 256>>>((const float4*)x, xhi, xlo, n4);
        n4 = 3 * CDIM * CDIM / 4;
        split_h<<<(n4 + 255) / 256, 256>>>((const float4*)w_qkv, whi, wlo, n4);
        n4 = CDIM * CDIM / 4;
        split_h<<<(n4 + 255) / 256, 256>>>((const float4*)w_proj, phi, plo, n4);
    }

    cudaFuncSetAttribute(gemm_f16s, cudaFuncAttributeMaxDynamicSharedMemorySize, GSMEM);

    // 1) QKV GEMM
    {
        dim3 grid((3 * CDIM) / 128, (M + 127) / 128);
        gemm_f16s<<<grid, 256, GSMEM>>>((const __half*)xhi, (const __half*)xlo,
                                        (const __half*)whi, (const __half*)wlo,
                                        nullptr, qkv_s, M, 3 * CDIM, CDIM);
    }

    // 2) attention (tensorized)
    {
        cudaFuncSetAttribute(attn_mma, cudaFuncAttributeMaxDynamicSharedMemorySize,
                             ATM_SMEM);
        attn_mma<<<BATCH * NH, 256, ATM_SMEM>>>(qkv_s, rpb, relidx, attn_s);
    }

    // 3) split attention output, then proj GEMM
    {
        int n4 = M * CDIM / 4;
        split_h<<<(n4 + 255) / 256, 256>>>((const float4*)attn_s, ahi, alo, n4);
        dim3 grid(CDIM / 128, (M + 127) / 128);
        gemm_f16s<<<grid, 256, GSMEM>>>((const __half*)ahi, (const __half*)alo,
                                        (const __half*)phi, (const __half*)plo,
                                        b_proj, out, M, CDIM, CDIM);
    }
}